// round 4
// baseline (speedup 1.0000x reference)
#include <cuda_runtime.h>
#include <cstdint>

#define M_DIM 32
#define K_DIM 16384
#define N_DIM 16384
#define SPLITS 8
#define KSPLIT (K_DIM / SPLITS)      // 2048
#define KC 256
#define NB_TILE 256
#define PADX 34                      // 136B rows: 8B-aligned, bank stride 2 (worst 2-way)

typedef unsigned long long ull;

// Static scratch (no allocation allowed)
__device__ float g_xT[K_DIM * M_DIM];            // 2 MB, xT[k][m] = relu(img)/128
__device__ float g_part[SPLITS * M_DIM * N_DIM]; // 16 MB split-K partials

__device__ __forceinline__ ull add2(ull a, ull b) {
    ull d;
    asm("add.rn.f32x2 %0, %1, %2;" : "=l"(d) : "l"(a), "l"(b));
    return d;
}

// ---------- kernel 1: xT[k][m] = relu(image[m][k]) / 128 ----------
__global__ void prep_xt_kernel(const float* __restrict__ img) {
    int i = blockIdx.x * blockDim.x + threadIdx.x;   // 524288
    int m = i >> 14;
    int k = i & (K_DIM - 1);
    float v = img[i];
    g_xT[k * M_DIM + m] = fmaxf(v, 0.f) * (1.0f / 128.0f);
}

// ---------- kernel 2: fused stream + ballot-transpose + ffs accumulate ----------
// grid (N/256 = 64, SPLITS = 8), 256 threads = 8 warps; warp w owns 32 n.
__global__ __launch_bounds__(256)
void spmm_fused(const float* __restrict__ V) {
    __shared__ __align__(16) float sx[KC * PADX];   // ~34.8 KB

    const int nb = blockIdx.x, kb = blockIdx.y;
    const int tid = threadIdx.x, w = tid >> 5, lane = tid & 31;
    const int n = nb * NB_TILE + w * 32 + lane;

    ull acc[16];
    #pragma unroll
    for (int q = 0; q < 16; ++q) acc[q] = 0ull;

    for (int c = 0; c < KSPLIT / KC; ++c) {
        const int k0 = kb * KSPLIT + c * KC;
        __syncthreads();
        // stage x chunk (float2 stores: row byte stride 136 is 8-aligned)
        {
            const float2* src = (const float2*)(g_xT + (size_t)k0 * M_DIM);
            for (int i = tid; i < KC * 16; i += 256) {
                int kk = i >> 4, q = i & 15;
                *(float2*)(sx + kk * PADX + q * 2) = src[i];
            }
        }
        __syncthreads();

        #pragma unroll 1
        for (int t = 0; t < KC / 32; ++t) {
            const float* vp = V + (size_t)(k0 + t * 32) * N_DIM + n;
            unsigned x = 0;
            // two batches of 16 rows: load (MLP=16), then ballot-transpose
            #pragma unroll
            for (int h = 0; h < 2; ++h) {
                float v[16];
                #pragma unroll
                for (int j = 0; j < 16; ++j)
                    v[j] = vp[(size_t)(h * 16 + j) * N_DIM];
                #pragma unroll
                for (int j = 0; j < 16; ++j) {
                    unsigned b = __ballot_sync(0xffffffffu, v[j] != 0.0f);
                    x |= ((b >> lane) & 1u) << (h * 16 + j);
                }
            }
            // lane-private sparse walk over its own k-bits
            while (x) {
                int j = __ffs(x) - 1;
                x &= x - 1;
                const ull* xs = (const ull*)(sx + (t * 32 + j) * PADX);
                #pragma unroll
                for (int q = 0; q < 16; ++q) acc[q] = add2(acc[q], xs[q]);
            }
        }
    }

    // split-K partials (every (m,n,kb) written exactly once -> no zero init)
    float* po = g_part + (size_t)kb * (M_DIM * N_DIM);
    #pragma unroll
    for (int q = 0; q < 16; ++q) {
        unsigned lo = (unsigned)(acc[q] & 0xffffffffull);
        unsigned hi = (unsigned)(acc[q] >> 32);
        po[(size_t)(2 * q) * N_DIM + n]     = __uint_as_float(lo);
        po[(size_t)(2 * q + 1) * N_DIM + n] = __uint_as_float(hi);
    }
}

// ---------- kernel 3: reduce split-K partials into d_out ----------
__global__ void reduce_kernel(float4* __restrict__ out) {
    int i = blockIdx.x * blockDim.x + threadIdx.x;   // 131072 float4
    const float4* p = (const float4*)g_part;
    float4 s = p[i];
    #pragma unroll
    for (int sp = 1; sp < SPLITS; ++sp) {
        float4 v = p[(size_t)sp * (M_DIM * N_DIM / 4) + i];
        s.x += v.x; s.y += v.y; s.z += v.z; s.w += v.w;
    }
    out[i] = s;
}

extern "C" void kernel_launch(void* const* d_in, const int* in_sizes, int n_in,
                              void* d_out, int out_size) {
    const float* img = (const float*)d_in[0];   // (2,16,128,128)
    const float* V   = (const float*)d_in[1];   // (128,128,128,128)
    float* out = (float*)d_out;

    (void)in_sizes; (void)n_in; (void)out_size;

    prep_xt_kernel<<<(K_DIM * M_DIM) / 256, 256>>>(img);

    dim3 grid(N_DIM / NB_TILE, SPLITS);   // (64, 8)
    spmm_fused<<<grid, 256>>>(V);

    reduce_kernel<<<(M_DIM * N_DIM / 4) / 256, 256>>>((float4*)out);
}

// round 5
// speedup vs baseline: 1.0537x; 1.0537x over previous
#include <cuda_runtime.h>
#include <cstdint>

#define M_DIM 32
#define K_DIM 16384
#define N_DIM 16384
#define SPLITS 8
#define KSPLIT (K_DIM / SPLITS)      // 2048
#define KCH 32                       // k rows per staged chunk
#define NCH (KSPLIT / KCH)           // 64 chunks per CTA
#define NB_TILE 256
#define PADX 34                      // x row pitch in floats (136B: 8B-aligned)

typedef unsigned long long ull;

// Static scratch (no allocation allowed)
__device__ float g_xT[K_DIM * M_DIM];            // 2 MB, xT[k][m] = relu(img)/128
__device__ float g_part[SPLITS * M_DIM * N_DIM]; // 16 MB split-K partials

__device__ __forceinline__ ull add2(ull a, ull b) {
    ull d;
    asm("add.rn.f32x2 %0, %1, %2;" : "=l"(d) : "l"(a), "l"(b));
    return d;
}

// ---------- kernel 1: tiled transpose, xT[k][m] = relu(image[m][k]) / 128 ----
__global__ void prep_xt_kernel(const float* __restrict__ img) {
    __shared__ float s[32][33];
    const int kb = blockIdx.x;          // 512 k-tiles
    const int tx = threadIdx.x, ty = threadIdx.y;   // (32, 8)
    #pragma unroll
    for (int r = 0; r < 4; ++r) {
        int m = ty + 8 * r;
        s[tx][m] = img[(size_t)m * K_DIM + kb * 32 + tx];   // coalesced read
    }
    __syncthreads();
    #pragma unroll
    for (int r = 0; r < 4; ++r) {
        int kl = ty + 8 * r;
        float v = s[kl][tx];
        g_xT[(size_t)(kb * 32 + kl) * M_DIM + tx] =
            fmaxf(v, 0.f) * (1.0f / 128.0f);                 // coalesced write
    }
}

// ---------- kernel 2: fused stream(smem-staged) + compress + ffs accumulate ----
// grid (64 n-tiles, 8 k-splits) = 512 CTAs, 256 threads; lane owns one n, all 32 m.
__global__ __launch_bounds__(256, 4)
void spmm_fused(const float* __restrict__ V) {
    __shared__ __align__(16) float sv[KCH * NB_TILE];   // 32 KB V chunk [k][n]
    __shared__ __align__(16) float sx[KCH * PADX];      // 4.25 KB x chunk

    const int nb = blockIdx.x, kb = blockIdx.y;
    const int tid = threadIdx.x, w = tid >> 5, lane = tid & 31;
    const int nloc = w * 32 + lane;     // 0..255
    const int n = nb * NB_TILE + nloc;

    ull acc[16];
    #pragma unroll
    for (int q = 0; q < 16; ++q) acc[q] = 0ull;

    for (int c = 0; c < NCH; ++c) {
        const int k0 = kb * KSPLIT + c * KCH;
        __syncthreads();   // previous chunk fully consumed

        // stage x chunk: 32 rows x 32 m -> padded rows (2 float2 per thread)
        {
            const float2* xs = (const float2*)(g_xT + (size_t)k0 * M_DIM);
            #pragma unroll
            for (int p = 0; p < 2; ++p) {
                int i = tid + p * 256;          // 0..511
                int kk = i >> 4, q = i & 15;
                *(float2*)(sx + kk * PADX + q * 2) = xs[i];
            }
        }
        // stage V chunk: 8 float4 per thread, warp reads 512B contiguous per row
        {
            #pragma unroll
            for (int p = 0; p < 8; ++p) {
                int i = tid + p * 256;          // 0..2047
                int kk = i >> 6, q = i & 63;    // row, float4-in-row
                float4 v = *(const float4*)(V + (size_t)(k0 + kk) * N_DIM
                                              + nb * NB_TILE + q * 4);
                *(float4*)(sv + kk * NB_TILE + q * 4) = v;
            }
        }
        __syncthreads();

        // build this lane's k-word from its n column (conflict-free LDS)
        unsigned x = 0;
        const float* col = sv + nloc;
        #pragma unroll
        for (int j = 0; j < 32; ++j) {
            if (col[j * NB_TILE] != 0.0f) x |= (1u << j);
        }
        // lane-private sparse walk
        while (x) {
            int j = __ffs(x) - 1;
            x &= x - 1;
            const ull* xr = (const ull*)(sx + j * PADX);
            #pragma unroll
            for (int q = 0; q < 16; ++q) acc[q] = add2(acc[q], xr[q]);
        }
    }

    // split-K partials (each (m,n,kb) written exactly once -> no zero init)
    float* po = g_part + (size_t)kb * (M_DIM * N_DIM);
    #pragma unroll
    for (int q = 0; q < 16; ++q) {
        unsigned lo = (unsigned)(acc[q] & 0xffffffffull);
        unsigned hi = (unsigned)(acc[q] >> 32);
        po[(size_t)(2 * q) * N_DIM + n]     = __uint_as_float(lo);
        po[(size_t)(2 * q + 1) * N_DIM + n] = __uint_as_float(hi);
    }
}

// ---------- kernel 3: reduce split-K partials into d_out ----------
__global__ void reduce_kernel(float4* __restrict__ out) {
    int i = blockIdx.x * blockDim.x + threadIdx.x;   // 131072 float4
    const float4* p = (const float4*)g_part;
    float4 s = p[i];
    #pragma unroll
    for (int sp = 1; sp < SPLITS; ++sp) {
        float4 v = p[(size_t)sp * (M_DIM * N_DIM / 4) + i];
        s.x += v.x; s.y += v.y; s.z += v.z; s.w += v.w;
    }
    out[i] = s;
}

extern "C" void kernel_launch(void* const* d_in, const int* in_sizes, int n_in,
                              void* d_out, int out_size) {
    const float* img = (const float*)d_in[0];   // (2,16,128,128)
    const float* V   = (const float*)d_in[1];   // (128,128,128,128)
    float* out = (float*)d_out;

    (void)in_sizes; (void)n_in; (void)out_size;

    prep_xt_kernel<<<K_DIM / 32, dim3(32, 8)>>>(img);

    dim3 grid(N_DIM / NB_TILE, SPLITS);   // (64, 8)
    spmm_fused<<<grid, 256>>>(V);

    reduce_kernel<<<(M_DIM * N_DIM / 4) / 256, 256>>>((float4*)out);
}

// round 6
// speedup vs baseline: 1.9580x; 1.8582x over previous
#include <cuda_runtime.h>
#include <cstdint>

#define M_DIM 32
#define K_DIM 16384
#define N_DIM 16384
#define SPLITS 8
#define KSPLIT (K_DIM / SPLITS)      // 2048
#define KCH 16                       // k rows per staged chunk
#define NCH (KSPLIT / KCH)           // 128 chunks per CTA
#define NB_TILE 256
#define PADX 34                      // x row pitch in floats (136B: 8B-aligned)

typedef unsigned long long ull;

// Static scratch (no allocation allowed)
__device__ float g_xT[K_DIM * M_DIM];            // 2 MB, xT[k][m] = relu(img)/128
__device__ float g_part[SPLITS * M_DIM * N_DIM]; // 16 MB split-K partials

__device__ __forceinline__ ull add2(ull a, ull b) {
    ull d;
    asm("add.rn.f32x2 %0, %1, %2;" : "=l"(d) : "l"(a), "l"(b));
    return d;
}
__device__ __forceinline__ void cp_async16(void* s, const void* g) {
    unsigned sa = (unsigned)__cvta_generic_to_shared(s);
    asm volatile("cp.async.cg.shared.global [%0], [%1], 16;" :: "r"(sa), "l"(g));
}
__device__ __forceinline__ void cp_async8(void* s, const void* g) {
    unsigned sa = (unsigned)__cvta_generic_to_shared(s);
    asm volatile("cp.async.ca.shared.global [%0], [%1], 8;" :: "r"(sa), "l"(g));
}

// ---------- kernel 1: tiled transpose, xT[k][m] = relu(image[m][k]) / 128 ----
__global__ void prep_xt_kernel(const float* __restrict__ img) {
    __shared__ float s[32][33];
    const int kb = blockIdx.x;                       // 512 k-tiles
    const int tx = threadIdx.x, ty = threadIdx.y;    // (32, 8)
    #pragma unroll
    for (int r = 0; r < 4; ++r) {
        int m = ty + 8 * r;
        s[tx][m] = img[(size_t)m * K_DIM + kb * 32 + tx];
    }
    __syncthreads();
    #pragma unroll
    for (int r = 0; r < 4; ++r) {
        int kl = ty + 8 * r;
        float v = s[kl][tx];
        g_xT[(size_t)(kb * 32 + kl) * M_DIM + tx] = fmaxf(v, 0.f) * (1.0f / 128.0f);
    }
}

// ---------- kernel 2: fused, cp.async double-buffered stream + ffs accumulate --
// grid (64 n-tiles, 8 k-splits) = 512 CTAs, 256 threads; lane owns one n, 32 m.
__global__ __launch_bounds__(256, 4)
void spmm_fused(const float* __restrict__ V) {
    __shared__ __align__(16) float sv[2][KCH * NB_TILE];  // 2 x 16 KB
    __shared__ __align__(16) float sx[2][KCH * PADX];     // 2 x 2.2 KB

    const int nb = blockIdx.x, kb = blockIdx.y;
    const int tid = threadIdx.x, lane = tid & 31;
    const int nloc = tid;                 // thread owns column nloc (0..255)
    const int n = nb * NB_TILE + nloc;
    (void)lane;

    ull acc[16];
    #pragma unroll
    for (int q = 0; q < 16; ++q) acc[q] = 0ull;

    // prefetch helper (inlined twice below via macro)
#define PREFETCH(cc, bb)                                                       \
    {                                                                          \
        const int pk0 = kb * KSPLIT + (cc) * KCH;                              \
        _Pragma("unroll")                                                      \
        for (int p = 0; p < 4; ++p) {          /* 16KB V chunk */              \
            int i = tid + p * 256;             /* 0..1023 float4 */            \
            int kk = i >> 6, q = i & 63;                                       \
            cp_async16(&sv[bb][kk * NB_TILE + q * 4],                          \
                       V + (size_t)(pk0 + kk) * N_DIM + nb * NB_TILE + q * 4); \
        }                                                                      \
        {                                      /* 2KB x chunk, padded rows */  \
            int kk = tid >> 4, q = tid & 15;                                   \
            cp_async8(&sx[bb][kk * PADX + q * 2],                              \
                      g_xT + (size_t)(pk0 + kk) * M_DIM + q * 2);              \
        }                                                                      \
    }

    PREFETCH(0, 0)
    asm volatile("cp.async.commit_group;");

    for (int c = 0; c < NCH; ++c) {
        const int buf = c & 1;
        if (c + 1 < NCH) PREFETCH(c + 1, (c + 1) & 1)
        asm volatile("cp.async.commit_group;");   // uniform group count
        asm volatile("cp.async.wait_group 1;");   // chunk c landed
        __syncthreads();

        // build this thread's 16-bit k-word from its n column (conflict-free LDS)
        unsigned x = 0;
        const float* col = &sv[buf][nloc];
        #pragma unroll
        for (int j = 0; j < KCH; ++j) {
            if (col[j * NB_TILE] != 0.0f) x |= (1u << j);
        }
        // lane-private sparse walk
        while (x) {
            int j = __ffs(x) - 1;
            x &= x - 1;
            const ull* xr = (const ull*)(&sx[buf][j * PADX]);
            #pragma unroll
            for (int q = 0; q < 16; ++q) acc[q] = add2(acc[q], xr[q]);
        }
        __syncthreads();   // buf consumed; safe to overwrite next iteration
    }
#undef PREFETCH

    // split-K partials (each (m,n,kb) written exactly once -> no zero init)
    float* po = g_part + (size_t)kb * (M_DIM * N_DIM);
    #pragma unroll
    for (int q = 0; q < 16; ++q) {
        unsigned lo = (unsigned)(acc[q] & 0xffffffffull);
        unsigned hi = (unsigned)(acc[q] >> 32);
        po[(size_t)(2 * q) * N_DIM + n]     = __uint_as_float(lo);
        po[(size_t)(2 * q + 1) * N_DIM + n] = __uint_as_float(hi);
    }
}

// ---------- kernel 3: reduce split-K partials into d_out ----------
__global__ void reduce_kernel(float4* __restrict__ out) {
    int i = blockIdx.x * blockDim.x + threadIdx.x;   // 131072 float4
    const float4* p = (const float4*)g_part;
    float4 s = p[i];
    #pragma unroll
    for (int sp = 1; sp < SPLITS; ++sp) {
        float4 v = p[(size_t)sp * (M_DIM * N_DIM / 4) + i];
        s.x += v.x; s.y += v.y; s.z += v.z; s.w += v.w;
    }
    out[i] = s;
}

extern "C" void kernel_launch(void* const* d_in, const int* in_sizes, int n_in,
                              void* d_out, int out_size) {
    const float* img = (const float*)d_in[0];   // (2,16,128,128)
    const float* V   = (const float*)d_in[1];   // (128,128,128,128)
    float* out = (float*)d_out;

    (void)in_sizes; (void)n_in; (void)out_size;

    prep_xt_kernel<<<K_DIM / 32, dim3(32, 8)>>>(img);

    dim3 grid(N_DIM / NB_TILE, SPLITS);   // (64, 8)
    spmm_fused<<<grid, 256>>>(V);

    reduce_kernel<<<(M_DIM * N_DIM / 4) / 256, 256>>>((float4*)out);
}

// round 8
// speedup vs baseline: 2.0136x; 1.0284x over previous
#include <cuda_runtime.h>
#include <cstdint>

#define M_DIM 32
#define K_DIM 16384
#define N_DIM 16384
#define SPLITS 8
#define KSPLIT (K_DIM / SPLITS)      // 2048
#define KCH 16                       // k rows per staged chunk
#define NCH (KSPLIT / KCH)           // 128 chunks per CTA
#define NB_TILE 256
#define PADX 34                      // x row pitch in floats (136B: 8B-aligned)

typedef unsigned long long ull;

// Static scratch (no allocation allowed)
__device__ float g_xT[K_DIM * M_DIM];            // 2 MB, xT[k][m] = relu(img)/128

__device__ __forceinline__ ull add2(ull a, ull b) {
    ull d;
    asm("add.rn.f32x2 %0, %1, %2;" : "=l"(d) : "l"(a), "l"(b));
    return d;
}
__device__ __forceinline__ void cp_async16(void* s, const void* g) {
    unsigned sa = (unsigned)__cvta_generic_to_shared(s);
    asm volatile("cp.async.cg.shared.global [%0], [%1], 16;" :: "r"(sa), "l"(g));
}
__device__ __forceinline__ void cp_async8(void* s, const void* g) {
    unsigned sa = (unsigned)__cvta_generic_to_shared(s);
    asm volatile("cp.async.ca.shared.global [%0], [%1], 8;" :: "r"(sa), "l"(g));
}

// ---------- kernel 1: transpose x (relu + /128) AND zero the poisoned out ----
__global__ void prep_xt_kernel(const float* __restrict__ img,
                               float4* __restrict__ out) {
    __shared__ float s[32][33];
    const int kb = blockIdx.x;                       // 512 tiles
    const int tx = threadIdx.x, ty = threadIdx.y;    // (32, 8)
    const int tid = ty * 32 + tx;

    // zero 1024 floats (256 float4) of out per CTA: 512*1024 = 524288 total
    out[(size_t)kb * 256 + tid] = make_float4(0.f, 0.f, 0.f, 0.f);

    #pragma unroll
    for (int r = 0; r < 4; ++r) {
        int m = ty + 8 * r;
        s[tx][m] = img[(size_t)m * K_DIM + kb * 32 + tx];
    }
    __syncthreads();
    #pragma unroll
    for (int r = 0; r < 4; ++r) {
        int kl = ty + 8 * r;
        float v = s[kl][tx];
        g_xT[(size_t)(kb * 32 + kl) * M_DIM + tx] = fmaxf(v, 0.f) * (1.0f / 128.0f);
    }
}

// ---------- kernel 2: fused, cp.async double-buffered stream + ffs accumulate --
// grid (64 n-tiles, 8 k-splits) = 512 CTAs, 256 threads; thread owns one n, 32 m.
__global__ __launch_bounds__(256, 4)
void spmm_fused(const float* __restrict__ V, float* __restrict__ out) {
    __shared__ __align__(16) float sv[2][KCH * NB_TILE];  // 2 x 16 KB
    __shared__ __align__(16) float sx[2][KCH * PADX];     // 2 x 2.2 KB

    const int nb = blockIdx.x, kb = blockIdx.y;
    const int tid = threadIdx.x;
    const int nloc = tid;                 // thread owns column nloc (0..255)
    const int n = nb * NB_TILE + nloc;

    ull acc[16];
    #pragma unroll
    for (int q = 0; q < 16; ++q) acc[q] = 0ull;

#define PREFETCH(cc, bb)                                                       \
    {                                                                          \
        const int pk0 = kb * KSPLIT + (cc) * KCH;                              \
        _Pragma("unroll")                                                      \
        for (int p = 0; p < 4; ++p) {          /* 16KB V chunk */              \
            int i = tid + p * 256;             /* 0..1023 float4 */            \
            int kk = i >> 6, q = i & 63;                                       \
            cp_async16(&sv[bb][kk * NB_TILE + q * 4],                          \
                       V + (size_t)(pk0 + kk) * N_DIM + nb * NB_TILE + q * 4); \
        }                                                                      \
        {                                      /* 2KB x chunk, padded rows */  \
            int kk = tid >> 4, q = tid & 15;                                   \
            cp_async8(&sx[bb][kk * PADX + q * 2],                              \
                      g_xT + (size_t)(pk0 + kk) * M_DIM + q * 2);              \
        }                                                                      \
    }

    PREFETCH(0, 0)
    asm volatile("cp.async.commit_group;");

    for (int c = 0; c < NCH; ++c) {
        const int buf = c & 1;
        if (c + 1 < NCH) PREFETCH(c + 1, (c + 1) & 1)
        asm volatile("cp.async.commit_group;");   // uniform group count
        asm volatile("cp.async.wait_group 1;");   // chunk c landed
        __syncthreads();

        // build this thread's 16-bit k-word from its n column (conflict-free LDS)
        unsigned x = 0;
        const float* col = &sv[buf][nloc];
        #pragma unroll
        for (int j = 0; j < KCH; ++j) {
            if (col[j * NB_TILE] != 0.0f) x |= (1u << j);
        }
        // lane-private sparse walk
        while (x) {
            int j = __ffs(x) - 1;
            x &= x - 1;
            const ull* xr = (const ull*)(&sx[buf][j * PADX]);
            #pragma unroll
            for (int q = 0; q < 16; ++q) acc[q] = add2(acc[q], xr[q]);
        }
        __syncthreads();   // buf consumed; safe to overwrite next iteration
    }
#undef PREFETCH

    // epilogue: combine split-K in place via no-return global reductions
    #pragma unroll
    for (int q = 0; q < 16; ++q) {
        float lo = __uint_as_float((unsigned)(acc[q] & 0xffffffffull));
        float hi = __uint_as_float((unsigned)(acc[q] >> 32));
        atomicAdd(&out[(size_t)(2 * q) * N_DIM + n], lo);
        atomicAdd(&out[(size_t)(2 * q + 1) * N_DIM + n], hi);
    }
}

extern "C" void kernel_launch(void* const* d_in, const int* in_sizes, int n_in,
                              void* d_out, int out_size) {
    const float* img = (const float*)d_in[0];   // (2,16,128,128)
    const float* V   = (const float*)d_in[1];   // (128,128,128,128)
    float* out = (float*)d_out;

    (void)in_sizes; (void)n_in; (void)out_size;

    prep_xt_kernel<<<K_DIM / 32, dim3(32, 8)>>>(img, (float4*)out);

    dim3 grid(N_DIM / NB_TILE, SPLITS);   // (64, 8)
    spmm_fused<<<grid, 256>>>(V, out);
}